// round 13
// baseline (speedup 1.0000x reference)
#include <cuda_runtime.h>
#include <cuda_fp16.h>
#include <cstdint>

#define BDIM   1024
#define BATCH  32
#define SEQ    2048
#define MROWS  (BATCH * SEQ)

#define BM 128
#define BN 128
#define BK 64                      // fp16: 64 halves = 128B row (swizzle atom)
#define KTILES (BDIM / BK)         // 16 k-iterations per unit
#define NPASS  (BDIM / BN)         // 8 n-passes
#define MTILES (MROWS / BM)        // 512
#define UNITS  (MTILES * NPASS)    // 4096 work units (m-tile, n-pass)
#define GRID   304                 // 2 CTAs/SM x 152 SMs, persistent
#define NSTG   3
#define STG_A     16384            // 128 rows x 128B
#define STG_B     16384
#define STG_BYTES (STG_A + STG_B)  // 32768
#define OFF_UQ    (NSTG * STG_BYTES)
#define SMEM_BYTES (OFF_UQ + 256)  // ~96.5 KB -> 2 CTAs/SM

#define XBLOCKS ((MROWS * (BDIM / 8)) / 256)   // 32768
#define WBLOCKS ((BDIM * (BDIM / 8)) / 256)    // 512

__device__ __half g_Xh[(size_t)MROWS * BDIM];   // 128 MiB fp16 mirror of X
__device__ __half g_Wh[BDIM * BDIM];
__device__ float  g_logits[MROWS];
__device__ unsigned g_qhead;                    // dynamic unit queue head

__device__ __forceinline__ uint32_t smem_u32(const void* p) {
    return (uint32_t)__cvta_generic_to_shared(p);
}
__device__ __forceinline__ void cp_async16(uint32_t saddr, const void* gaddr) {
    asm volatile("cp.async.cg.shared.global [%0], [%1], 16;\n" :: "r"(saddr), "l"(gaddr));
}
__device__ __forceinline__ uint32_t swz(uint32_t off) {   // SW128: bits[6:4] ^= bits[9:7]
    return off ^ ((off >> 3) & 0x70u);
}
__device__ __forceinline__ float tanh_ap(float x) {
    float y; asm("tanh.approx.f32 %0, %1;" : "=f"(y) : "f"(x)); return y;
}
__device__ __forceinline__ void ldsm_x4(uint32_t& r0, uint32_t& r1, uint32_t& r2,
                                        uint32_t& r3, uint32_t addr) {
    asm volatile("ldmatrix.sync.aligned.m8n8.x4.shared.b16 {%0,%1,%2,%3}, [%4];"
                 : "=r"(r0), "=r"(r1), "=r"(r2), "=r"(r3) : "r"(addr));
}

// ---------------------------------------------------------------------------
// no-op kernel: keeps ncu capture (-s 5) aligned on logits_kernel
// ---------------------------------------------------------------------------
__global__ void noop_kernel() {}

// ---------------------------------------------------------------------------
// fp32 -> fp16 bulk convert of X and W; W-half blocks also zero g_logits and
// reset the work-queue head (graph replays the whole sequence every launch).
// ---------------------------------------------------------------------------
__global__ void cvt_all_kernel(const float* __restrict__ X, const float* __restrict__ W) {
    const float* src;
    __half* dst;
    size_t i;
    if (blockIdx.x < XBLOCKS) {
        src = X; dst = g_Xh;
        i = ((size_t)blockIdx.x * 256 + threadIdx.x) * 8;
    } else {
        src = W; dst = g_Wh;
        int z = (blockIdx.x - XBLOCKS) * 256 + threadIdx.x;   // 0..131071
        if (z < MROWS) g_logits[z] = 0.0f;
        if (z == 0) g_qhead = GRID;                            // units 0..GRID-1 pre-assigned
        i = ((size_t)(blockIdx.x - XBLOCKS) * 256 + threadIdx.x) * 8;
    }
    float4 f0 = *(const float4*)(src + i);
    float4 f1 = *(const float4*)(src + i + 4);
    __half2 h[4];
    h[0] = __float22half2_rn({f0.x, f0.y});
    h[1] = __float22half2_rn({f0.z, f0.w});
    h[2] = __float22half2_rn({f1.x, f1.y});
    h[3] = __float22half2_rn({f1.z, f1.w});
    *(uint4*)(dst + i) = *(uint4*)h;
}

// ---------------------------------------------------------------------------
// tile loader for (unit u, k-chunk kt) into ring stage stg.
// Sentinel units (u >= UNITS) skip the loads but STILL commit an (empty)
// group so every thread's wait_group count stays uniform.
// ---------------------------------------------------------------------------
__device__ __forceinline__ void load_tile(char* smem, int u, int kt, int stg, int tid) {
    if (u < UNITS) {
        const int m0 = (u >> 3) * BM;
        const int nt = u & 7;
        const uint32_t base = smem_u32(smem) + (uint32_t)stg * STG_BYTES;
        const int r  = tid >> 3;                  // 0..15
        const int cb = (tid & 7) * 16;            // byte col in 128B row
        const __half* Xb = g_Xh + (size_t)(m0 + r) * BDIM + kt * BK + (cb >> 1);
        #pragma unroll
        for (int i = 0; i < 8; ++i) {
            uint32_t off = (uint32_t)(r + 16 * i) * 128u + (uint32_t)cb;
            cp_async16(base + swz(off), Xb + (size_t)(16 * i) * BDIM);
        }
        const __half* Wb = g_Wh + (size_t)(nt * BN + r) * BDIM + kt * BK + (cb >> 1);
        #pragma unroll
        for (int i = 0; i < 8; ++i) {
            uint32_t off = (uint32_t)(r + 16 * i) * 128u + (uint32_t)cb;
            cp_async16(base + STG_A + swz(off), Wb + (size_t)(16 * i) * BDIM);
        }
    }
    asm volatile("cp.async.commit_group;\n" ::: "memory");
}

// ---------------------------------------------------------------------------
// Kernel A: logits[m] = sum_e v[e] * tanh( sum_d X[m,d] W[e,d] )
// Persistent DYNAMIC work queue: 304 CTAs fetch (m-tile, n-pass) units via a
// global atomic as their 3-stage pipeline rolls. Unit ids travel through a
// smem ring whose visibility rides the existing named-barrier arrive/sync.
// ---------------------------------------------------------------------------
__global__ __launch_bounds__(128, 2)
void logits_kernel(const float* __restrict__ v) {
    extern __shared__ char smem[];
    int* uq = (int*)(smem + OFF_UQ);   // 4-slot unit ring

    const int tid  = threadIdx.x;
    const int warp = tid >> 5;
    const int lane = tid & 31;
    const int wm = warp >> 1;           // 0..1  -> 64-row group
    const int wn = warp & 1;            // 0..1  -> 64-col group
    const int l4 = lane & 3;
    const int lg = lane >> 2;
    const int bid = blockIdx.x;

    const uint32_t sb = smem_u32(smem);
    const uint32_t a_row = (uint32_t)(wm * 64 + (lane & 15));
    const uint32_t a_kb  = (uint32_t)((lane >> 4) * 16);
    const uint32_t b_idx = (uint32_t)(lane & 7);
    const uint32_t b_sel = (uint32_t)(lane >> 3);
    const uint32_t b_row = (uint32_t)(wn * 64 + (b_sel >> 1) * 8) + b_idx;
    const uint32_t b_kb  = (b_sel & 1) * 16u;

    if (tid == 0) uq[0] = bid;          // first unit: static = blockIdx.x

    // prologue: tiles 0, 1 of unit bid; make tile 0 visible to all threads
    load_tile(smem, bid, 0, 0, tid);
    load_tile(smem, bid, 1, 1, tid);
    asm volatile("cp.async.wait_group 1;" ::: "memory");
    __syncthreads();

    float part[8];
    #pragma unroll
    for (int p = 0; p < 8; ++p) part[p] = 0.0f;
    float acc[4][8][4];

    uint32_t af[4][16];   // [ks][mi*4+q]
    uint32_t bf[4][16];   // [ks][j*2+q]

#define LDSM_KS(ks) do {                                                          \
    _Pragma("unroll")                                                             \
    for (int mi = 0; mi < 4; ++mi) {                                              \
        uint32_t off = (a_row + mi * 16u) * 128u + (uint32_t)((ks) * 32) + a_kb;  \
        ldsm_x4(af[ks][mi*4+0], af[ks][mi*4+1], af[ks][mi*4+2], af[ks][mi*4+3],   \
                stage + swz(off));                                                \
    }                                                                             \
    _Pragma("unroll")                                                             \
    for (int jj = 0; jj < 4; ++jj) {                                              \
        uint32_t off = (b_row + jj * 16u) * 128u + (uint32_t)((ks) * 32) + b_kb;  \
        ldsm_x4(bf[ks][jj*4+0], bf[ks][jj*4+1], bf[ks][jj*4+2], bf[ks][jj*4+3],   \
                stage + STG_A + swz(off));                                        \
    }                                                                             \
} while (0)

#define MMA_KS(ks) do {                                                           \
    _Pragma("unroll")                                                             \
    for (int mi = 0; mi < 4; ++mi) {                                              \
        _Pragma("unroll")                                                         \
        for (int j = 0; j < 8; ++j) {                                             \
            asm volatile(                                                         \
                "mma.sync.aligned.m16n8k16.row.col.f32.f16.f16.f32 "              \
                "{%0,%1,%2,%3}, {%4,%5,%6,%7}, {%8,%9}, {%0,%1,%2,%3};\n"         \
                : "+f"(acc[mi][j][0]), "+f"(acc[mi][j][1]),                       \
                  "+f"(acc[mi][j][2]), "+f"(acc[mi][j][3])                        \
                : "r"(af[ks][mi*4+0]), "r"(af[ks][mi*4+1]),                       \
                  "r"(af[ks][mi*4+2]), "r"(af[ks][mi*4+3]),                       \
                  "r"(bf[ks][j*2+0]), "r"(bf[ks][j*2+1]));                        \
        }                                                                         \
    }                                                                             \
} while (0)

    int u_cur = bid;
    for (int L = 0;; ++L) {
        const int kt = L & (KTILES - 1);

        // wait on the barrier instance opened at iteration L-1 (ids 1 / 2)
        if (L > 0)
            asm volatile("bar.sync %0, %1;" :: "r"(1 + ((L - 1) & 1)), "r"(256) : "memory");

        if (kt == 0) {
            u_cur = uq[(L >> 4) & 3];
            if (u_cur >= UNITS) break;     // queue drained: pipeline done
            #pragma unroll
            for (int i = 0; i < 4; ++i)
                #pragma unroll
                for (int j = 0; j < 8; ++j)
                    #pragma unroll
                    for (int q = 0; q < 4; ++q) acc[i][j][q] = 0.0f;
        }

        // fetch-ahead: unit for tile L+3 (visible to peers after arrive/sync)
        if (((L + 3) & 15) == 0 && tid == 0)
            uq[((L + 3) >> 4) & 3] = (int)atomicAdd(&g_qhead, 1u);

        // load tile L+2 (buffer reuse guarded by the bar.sync above)
        load_tile(smem, uq[((L + 2) >> 4) & 3], (L + 2) & 15, (L + 2) % NSTG, tid);

        const uint32_t stage = sb + (uint32_t)(L % NSTG) * STG_BYTES;

        LDSM_KS(0);
        LDSM_KS(1);
        MMA_KS(0);
        LDSM_KS(2);
        MMA_KS(1);
        LDSM_KS(3);

        // my loads for tile L+1 are complete (keep L+2 pending)
        asm volatile("cp.async.wait_group 1;" ::: "memory");

        // signal: my ldsm of buffer L done + my tile-(L+1) loads landed
        asm volatile("bar.arrive %0, %1;" :: "r"(1 + (L & 1)), "r"(256) : "memory");

        MMA_KS(2);
        MMA_KS(3);

        // unit epilogue: tanh + v-dot, reduce, atomicAdd into g_logits
        if (kt == KTILES - 1) {
            const int m0 = (u_cur >> 3) * BM;
            const int nt = u_cur & 7;
            #pragma unroll
            for (int mi = 0; mi < 4; ++mi) {
                #pragma unroll
                for (int j = 0; j < 8; ++j) {
                    int c = nt * BN + wn * 64 + j * 8 + l4 * 2;
                    float v0 = __ldg(&v[c]);
                    float v1 = __ldg(&v[c + 1]);
                    part[mi * 2 + 0] += v0 * tanh_ap(acc[mi][j][0])
                                      + v1 * tanh_ap(acc[mi][j][1]);
                    part[mi * 2 + 1] += v0 * tanh_ap(acc[mi][j][2])
                                      + v1 * tanh_ap(acc[mi][j][3]);
                }
            }
            #pragma unroll
            for (int p = 0; p < 8; ++p) {
                part[p] += __shfl_xor_sync(0xffffffffu, part[p], 1);
                part[p] += __shfl_xor_sync(0xffffffffu, part[p], 2);
            }
            if (l4 == 0) {
                #pragma unroll
                for (int mi = 0; mi < 4; ++mi) {
                    int row = m0 + wm * 64 + mi * 16 + lg;
                    atomicAdd(&g_logits[row],     part[mi * 2 + 0]);
                    atomicAdd(&g_logits[row + 8], part[mi * 2 + 1]);
                }
            }
            #pragma unroll
            for (int p = 0; p < 8; ++p) part[p] = 0.0f;
        }
    }
#undef LDSM_KS
#undef MMA_KS

    asm volatile("cp.async.wait_group 0;" ::: "memory");   // drain before exit
}

// ---------------------------------------------------------------------------
// Kernel B: softmax over S=2048 per batch (bias b cancels). Zeroes wc region.
// ---------------------------------------------------------------------------
__global__ void softmax_kernel(float* __restrict__ out) {
    __shared__ float red[8];
    const int b = blockIdx.x;
    const int tid = threadIdx.x;
    const int warp = tid >> 5, lane = tid & 31;
    const float* lp = g_logits + b * SEQ;

    float vals[8];
    float m = -1e30f;
    #pragma unroll
    for (int i = 0; i < 8; ++i) { vals[i] = lp[i * 256 + tid]; m = fmaxf(m, vals[i]); }
    #pragma unroll
    for (int o = 16; o > 0; o >>= 1) m = fmaxf(m, __shfl_xor_sync(~0u, m, o));
    if (lane == 0) red[warp] = m;
    __syncthreads();
    float bm = red[0];
    #pragma unroll
    for (int w = 1; w < 8; ++w) bm = fmaxf(bm, red[w]);
    __syncthreads();

    float s = 0.0f;
    #pragma unroll
    for (int i = 0; i < 8; ++i) { vals[i] = __expf(vals[i] - bm); s += vals[i]; }
    #pragma unroll
    for (int o = 16; o > 0; o >>= 1) s += __shfl_xor_sync(~0u, s, o);
    if (lane == 0) red[warp] = s;
    __syncthreads();
    float ts = 0.0f;
    #pragma unroll
    for (int w = 0; w < 8; ++w) ts += red[w];

    float inv = 1.0f / ts;
    #pragma unroll
    for (int i = 0; i < 8; ++i)
        out[BATCH * BDIM + b * SEQ + i * 256 + tid] = vals[i] * inv;

    for (int d = tid; d < BDIM; d += 256) out[b * BDIM + d] = 0.0f;
}

// ---------------------------------------------------------------------------
// Kernel C: weighted_context[b,d] = sum_s attn[b,s] * X[b,s,d]
// 512 CTAs (16 s-chunks x 32 batches), 128 thr x 8 d's (one uint4/row),
// attn chunk staged in smem.
// ---------------------------------------------------------------------------
__global__ __launch_bounds__(128)
void weighted_kernel(float* __restrict__ out) {
    __shared__ float aw[128];
    const int b  = blockIdx.z;
    const int s0 = blockIdx.y * 128;
    const int d8 = threadIdx.x * 8;

    aw[threadIdx.x] = out[BATCH * BDIM + b * SEQ + s0 + threadIdx.x];
    __syncthreads();

    const __half* xb = g_Xh + ((size_t)b * SEQ + s0) * BDIM + d8;

    float acc[8] = {0.f, 0.f, 0.f, 0.f, 0.f, 0.f, 0.f, 0.f};
    #pragma unroll 4
    for (int s = 0; s < 128; ++s) {
        uint4 raw = *(const uint4*)(xb + (size_t)s * BDIM);
        const __half2* h = (const __half2*)&raw;
        float w = aw[s];
        #pragma unroll
        for (int q = 0; q < 4; ++q) {
            float2 x = __half22float2(h[q]);
            acc[2*q]     += w * x.x;
            acc[2*q + 1] += w * x.y;
        }
    }
    #pragma unroll
    for (int q = 0; q < 8; ++q)
        atomicAdd(&out[b * BDIM + d8 + q], acc[q]);
}

// ---------------------------------------------------------------------------
extern "C" void kernel_launch(void* const* d_in, const int* in_sizes, int n_in,
                              void* d_out, int out_size) {
    const float* X = (const float*)d_in[0];   // context [32,2048,1024]
    const float* W = (const float*)d_in[1];   // [1024,1024]
    const float* v = (const float*)d_in[2];   // [1024]
    float* out = (float*)d_out;               // [wc 32*1024 | attn 32*2048]

    cvt_all_kernel<<<XBLOCKS + WBLOCKS, 256>>>(X, W);
    noop_kernel<<<1, 32>>>();                 // ncu alignment: -s 5 -> logits
    noop_kernel<<<1, 32>>>();

    cudaFuncSetAttribute(logits_kernel,
                         cudaFuncAttributeMaxDynamicSharedMemorySize, SMEM_BYTES);
    logits_kernel<<<GRID, 128, SMEM_BYTES>>>(v);
    softmax_kernel<<<BATCH, 256>>>(out);
    weighted_kernel<<<dim3(1, 16, BATCH), 128>>>(out);
}

// round 14
// speedup vs baseline: 1.0456x; 1.0456x over previous
#include <cuda_runtime.h>
#include <cuda_fp16.h>
#include <cstdint>

#define BDIM   1024
#define BATCH  32
#define SEQ    2048
#define MROWS  (BATCH * SEQ)

#define BM 128
#define BN 128
#define BK 64                      // fp16: 64 halves = 128B row (swizzle atom)
#define KTILES (BDIM / BK)         // 16 k-iterations per unit
#define NPASS  (BDIM / BN)         // 8 n-passes
#define MTILES (MROWS / BM)        // 512
#define UNITS  (MTILES * NPASS)    // 4096 work units (m-tile, n-pass)
#define GRID   304                 // 2 CTAs/SM x 152 SMs, persistent
#define NSTG   3
#define STG_A     16384            // 128 rows x 128B
#define STG_B     16384
#define STG_BYTES (STG_A + STG_B)  // 32768
#define SMEM_BYTES (NSTG * STG_BYTES + 256)   // ~96.5 KB -> 2 CTAs/SM

#define XBLOCKS ((MROWS * (BDIM / 8)) / 256)   // 32768
#define WBLOCKS ((BDIM * (BDIM / 8)) / 256)    // 512

__device__ __half g_Xh[(size_t)MROWS * BDIM];   // 128 MiB fp16 mirror of X
__device__ __half g_Wh[BDIM * BDIM];
__device__ float  g_logits[MROWS];

__device__ __forceinline__ uint32_t smem_u32(const void* p) {
    return (uint32_t)__cvta_generic_to_shared(p);
}
__device__ __forceinline__ void cp_async16(uint32_t saddr, const void* gaddr) {
    asm volatile("cp.async.cg.shared.global [%0], [%1], 16;\n" :: "r"(saddr), "l"(gaddr));
}
__device__ __forceinline__ uint32_t swz(uint32_t off) {   // SW128: bits[6:4] ^= bits[9:7]
    return off ^ ((off >> 3) & 0x70u);
}
__device__ __forceinline__ float tanh_ap(float x) {
    float y; asm("tanh.approx.f32 %0, %1;" : "=f"(y) : "f"(x)); return y;
}
__device__ __forceinline__ void ldsm_x4(uint32_t& r0, uint32_t& r1, uint32_t& r2,
                                        uint32_t& r3, uint32_t addr) {
    asm volatile("ldmatrix.sync.aligned.m8n8.x4.shared.b16 {%0,%1,%2,%3}, [%4];"
                 : "=r"(r0), "=r"(r1), "=r"(r2), "=r"(r3) : "r"(addr));
}

// ---------------------------------------------------------------------------
// no-op kernel: keeps ncu capture (-s 5) aligned on logits_kernel
// ---------------------------------------------------------------------------
__global__ void noop_kernel() {}

// ---------------------------------------------------------------------------
// fp32 -> fp16 bulk convert of X and W; W-half blocks also zero g_logits
// (logits is accumulated with atomics -> must be zeroed EVERY launch).
// ---------------------------------------------------------------------------
__global__ void cvt_all_kernel(const float* __restrict__ X, const float* __restrict__ W) {
    const float* src;
    __half* dst;
    size_t i;
    if (blockIdx.x < XBLOCKS) {
        src = X; dst = g_Xh;
        i = ((size_t)blockIdx.x * 256 + threadIdx.x) * 8;
    } else {
        src = W; dst = g_Wh;
        int z = (blockIdx.x - XBLOCKS) * 256 + threadIdx.x;   // 0..131071
        if (z < MROWS) g_logits[z] = 0.0f;
        i = ((size_t)(blockIdx.x - XBLOCKS) * 256 + threadIdx.x) * 8;
    }
    float4 f0 = *(const float4*)(src + i);
    float4 f1 = *(const float4*)(src + i + 4);
    __half2 h[4];
    h[0] = __float22half2_rn({f0.x, f0.y});
    h[1] = __float22half2_rn({f0.z, f0.w});
    h[2] = __float22half2_rn({f1.x, f1.y});
    h[3] = __float22half2_rn({f1.z, f1.w});
    *(uint4*)(dst + i) = *(uint4*)h;
}

// ---------------------------------------------------------------------------
// tile loader for flat local iteration L of this CTA:
// unit u = bid + (L/16)*GRID, kt = L%16, m0 = (u/8)*128, nt = u%8.
// A (128 x 64 fp16) + B (128 x 64 fp16), SW128 smem; 16 cp.async/thread.
// ---------------------------------------------------------------------------
__device__ __forceinline__ void load_tile(char* smem, int L, int bid, int tid) {
    const int u  = bid + (L >> 4) * GRID;
    const int kt = L & (KTILES - 1);
    const int m0 = (u >> 3) * BM;
    const int nt = u & 7;
    const uint32_t base = smem_u32(smem) + (uint32_t)(L % NSTG) * STG_BYTES;
    const int r  = tid >> 3;                  // 0..15
    const int cb = (tid & 7) * 16;            // byte col in 128B row
    const __half* Xb = g_Xh + (size_t)(m0 + r) * BDIM + kt * BK + (cb >> 1);
    #pragma unroll
    for (int i = 0; i < 8; ++i) {
        uint32_t off = (uint32_t)(r + 16 * i) * 128u + (uint32_t)cb;
        cp_async16(base + swz(off), Xb + (size_t)(16 * i) * BDIM);
    }
    const __half* Wb = g_Wh + (size_t)(nt * BN + r) * BDIM + kt * BK + (cb >> 1);
    #pragma unroll
    for (int i = 0; i < 8; ++i) {
        uint32_t off = (uint32_t)(r + 16 * i) * 128u + (uint32_t)cb;
        cp_async16(base + STG_A + swz(off), Wb + (size_t)(16 * i) * BDIM);
    }
    asm volatile("cp.async.commit_group;\n" ::: "memory");
}

// ---------------------------------------------------------------------------
// Kernel A: logits[m] = sum_e v[e] * tanh( sum_d X[m,d] W[e,d] )
// Persistent STATIC work queue (round-12 structure): 304 CTAs, units
// (m-tile, n-pass), one continuous 3-stage pipeline across units.
// Named-barrier arrive/sync split; per-unit epilogue atomicAdds into logits.
// ---------------------------------------------------------------------------
__global__ __launch_bounds__(128, 2)
void logits_kernel(const float* __restrict__ v) {
    extern __shared__ char smem[];

    const int tid  = threadIdx.x;
    const int warp = tid >> 5;
    const int lane = tid & 31;
    const int wm = warp >> 1;           // 0..1  -> 64-row group
    const int wn = warp & 1;            // 0..1  -> 64-col group
    const int l4 = lane & 3;
    const int lg = lane >> 2;
    const int bid = blockIdx.x;

    // units for this CTA: bid, bid+GRID, ...  (13 or 14)
    const int nu   = (UNITS - bid + GRID - 1) / GRID;
    const int LTOT = nu * KTILES;

    const uint32_t sb = smem_u32(smem);
    const uint32_t a_row = (uint32_t)(wm * 64 + (lane & 15));
    const uint32_t a_kb  = (uint32_t)((lane >> 4) * 16);
    const uint32_t b_idx = (uint32_t)(lane & 7);
    const uint32_t b_sel = (uint32_t)(lane >> 3);
    const uint32_t b_row = (uint32_t)(wn * 64 + (b_sel >> 1) * 8) + b_idx;
    const uint32_t b_kb  = (b_sel & 1) * 16u;

    // prologue: tiles 0, 1; make tile 0 visible to all threads
    load_tile(smem, 0, bid, tid);
    load_tile(smem, 1, bid, tid);
    asm volatile("cp.async.wait_group 1;" ::: "memory");
    __syncthreads();

    float part[8];
    #pragma unroll
    for (int p = 0; p < 8; ++p) part[p] = 0.0f;
    float acc[4][8][4];

    uint32_t af[4][16];   // [ks][mi*4+q]
    uint32_t bf[4][16];   // [ks][j*2+q]

#define LDSM_KS(ks) do {                                                          \
    _Pragma("unroll")                                                             \
    for (int mi = 0; mi < 4; ++mi) {                                              \
        uint32_t off = (a_row + mi * 16u) * 128u + (uint32_t)((ks) * 32) + a_kb;  \
        ldsm_x4(af[ks][mi*4+0], af[ks][mi*4+1], af[ks][mi*4+2], af[ks][mi*4+3],   \
                stage + swz(off));                                                \
    }                                                                             \
    _Pragma("unroll")                                                             \
    for (int jj = 0; jj < 4; ++jj) {                                              \
        uint32_t off = (b_row + jj * 16u) * 128u + (uint32_t)((ks) * 32) + b_kb;  \
        ldsm_x4(bf[ks][jj*4+0], bf[ks][jj*4+1], bf[ks][jj*4+2], bf[ks][jj*4+3],   \
                stage + STG_A + swz(off));                                        \
    }                                                                             \
} while (0)

#define MMA_KS(ks) do {                                                           \
    _Pragma("unroll")                                                             \
    for (int mi = 0; mi < 4; ++mi) {                                              \
        _Pragma("unroll")                                                         \
        for (int j = 0; j < 8; ++j) {                                             \
            asm volatile(                                                         \
                "mma.sync.aligned.m16n8k16.row.col.f32.f16.f16.f32 "              \
                "{%0,%1,%2,%3}, {%4,%5,%6,%7}, {%8,%9}, {%0,%1,%2,%3};\n"         \
                : "+f"(acc[mi][j][0]), "+f"(acc[mi][j][1]),                       \
                  "+f"(acc[mi][j][2]), "+f"(acc[mi][j][3])                        \
                : "r"(af[ks][mi*4+0]), "r"(af[ks][mi*4+1]),                       \
                  "r"(af[ks][mi*4+2]), "r"(af[ks][mi*4+3]),                       \
                  "r"(bf[ks][j*2+0]), "r"(bf[ks][j*2+1]));                        \
        }                                                                         \
    }                                                                             \
} while (0)

    for (int L = 0; L < LTOT; ++L) {
        const int kt = L & (KTILES - 1);

        // wait on the instance opened at iteration L-1 (ids 1 / 2)
        if (L > 0)
            asm volatile("bar.sync %0, %1;" :: "r"(1 + ((L - 1) & 1)), "r"(256) : "memory");

        if (L + 2 < LTOT) load_tile(smem, L + 2, bid, tid);

        if (kt == 0) {
            #pragma unroll
            for (int i = 0; i < 4; ++i)
                #pragma unroll
                for (int j = 0; j < 8; ++j)
                    #pragma unroll
                    for (int q = 0; q < 4; ++q) acc[i][j][q] = 0.0f;
        }

        const uint32_t stage = sb + (uint32_t)(L % NSTG) * STG_BYTES;

        LDSM_KS(0);
        LDSM_KS(1);
        MMA_KS(0);
        LDSM_KS(2);
        MMA_KS(1);
        LDSM_KS(3);

        // my loads for tile L+1 are complete (keep L+2 pending)
        if (L < LTOT - 2) asm volatile("cp.async.wait_group 1;" ::: "memory");
        else              asm volatile("cp.async.wait_group 0;" ::: "memory");

        // signal: my ldsm of buffer L done + my tile-(L+1) loads landed
        if (L + 1 < LTOT)
            asm volatile("bar.arrive %0, %1;" :: "r"(1 + (L & 1)), "r"(256) : "memory");

        MMA_KS(2);
        MMA_KS(3);

        // unit epilogue: tanh + v-dot, reduce, atomicAdd into g_logits
        if (kt == KTILES - 1) {
            const int u  = bid + (L >> 4) * GRID;
            const int m0 = (u >> 3) * BM;
            const int nt = u & 7;
            #pragma unroll
            for (int j = 0; j < 8; ++j) {
                const int c = nt * BN + wn * 64 + j * 8 + l4 * 2;
                const float2 vv = *(const float2*)(v + c);   // one LDG.64, reused by all mi
                #pragma unroll
                for (int mi = 0; mi < 4; ++mi) {
                    part[mi * 2 + 0] += vv.x * tanh_ap(acc[mi][j][0])
                                      + vv.y * tanh_ap(acc[mi][j][1]);
                    part[mi * 2 + 1] += vv.x * tanh_ap(acc[mi][j][2])
                                      + vv.y * tanh_ap(acc[mi][j][3]);
                }
            }
            #pragma unroll
            for (int p = 0; p < 8; ++p) {
                part[p] += __shfl_xor_sync(0xffffffffu, part[p], 1);
                part[p] += __shfl_xor_sync(0xffffffffu, part[p], 2);
            }
            if (l4 == 0) {
                #pragma unroll
                for (int mi = 0; mi < 4; ++mi) {
                    int row = m0 + wm * 64 + mi * 16 + lg;
                    atomicAdd(&g_logits[row],     part[mi * 2 + 0]);
                    atomicAdd(&g_logits[row + 8], part[mi * 2 + 1]);
                }
            }
            #pragma unroll
            for (int p = 0; p < 8; ++p) part[p] = 0.0f;
        }
    }
#undef LDSM_KS
#undef MMA_KS
}

// ---------------------------------------------------------------------------
// Kernel B: softmax over S=2048 per batch (bias b cancels). Zeroes wc region.
// ---------------------------------------------------------------------------
__global__ void softmax_kernel(float* __restrict__ out) {
    __shared__ float red[8];
    const int b = blockIdx.x;
    const int tid = threadIdx.x;
    const int warp = tid >> 5, lane = tid & 31;
    const float* lp = g_logits + b * SEQ;

    float vals[8];
    float m = -1e30f;
    #pragma unroll
    for (int i = 0; i < 8; ++i) { vals[i] = lp[i * 256 + tid]; m = fmaxf(m, vals[i]); }
    #pragma unroll
    for (int o = 16; o > 0; o >>= 1) m = fmaxf(m, __shfl_xor_sync(~0u, m, o));
    if (lane == 0) red[warp] = m;
    __syncthreads();
    float bm = red[0];
    #pragma unroll
    for (int w = 1; w < 8; ++w) bm = fmaxf(bm, red[w]);
    __syncthreads();

    float s = 0.0f;
    #pragma unroll
    for (int i = 0; i < 8; ++i) { vals[i] = __expf(vals[i] - bm); s += vals[i]; }
    #pragma unroll
    for (int o = 16; o > 0; o >>= 1) s += __shfl_xor_sync(~0u, s, o);
    if (lane == 0) red[warp] = s;
    __syncthreads();
    float ts = 0.0f;
    #pragma unroll
    for (int w = 0; w < 8; ++w) ts += red[w];

    float inv = 1.0f / ts;
    #pragma unroll
    for (int i = 0; i < 8; ++i)
        out[BATCH * BDIM + b * SEQ + i * 256 + tid] = vals[i] * inv;

    for (int d = tid; d < BDIM; d += 256) out[b * BDIM + d] = 0.0f;
}

// ---------------------------------------------------------------------------
// Kernel C: weighted_context[b,d] = sum_s attn[b,s] * X[b,s,d]
// 512 CTAs (16 s-chunks x 32 batches), 128 thr x 8 d's (one uint4/row),
// attn chunk staged in smem.
// ---------------------------------------------------------------------------
__global__ __launch_bounds__(128)
void weighted_kernel(float* __restrict__ out) {
    __shared__ float aw[128];
    const int b  = blockIdx.z;
    const int s0 = blockIdx.y * 128;
    const int d8 = threadIdx.x * 8;

    aw[threadIdx.x] = out[BATCH * BDIM + b * SEQ + s0 + threadIdx.x];
    __syncthreads();

    const __half* xb = g_Xh + ((size_t)b * SEQ + s0) * BDIM + d8;

    float acc[8] = {0.f, 0.f, 0.f, 0.f, 0.f, 0.f, 0.f, 0.f};
    #pragma unroll 4
    for (int s = 0; s < 128; ++s) {
        uint4 raw = *(const uint4*)(xb + (size_t)s * BDIM);
        const __half2* h = (const __half2*)&raw;
        float w = aw[s];
        #pragma unroll
        for (int q = 0; q < 4; ++q) {
            float2 x = __half22float2(h[q]);
            acc[2*q]     += w * x.x;
            acc[2*q + 1] += w * x.y;
        }
    }
    #pragma unroll
    for (int q = 0; q < 8; ++q)
        atomicAdd(&out[b * BDIM + d8 + q], acc[q]);
}

// ---------------------------------------------------------------------------
extern "C" void kernel_launch(void* const* d_in, const int* in_sizes, int n_in,
                              void* d_out, int out_size) {
    const float* X = (const float*)d_in[0];   // context [32,2048,1024]
    const float* W = (const float*)d_in[1];   // [1024,1024]
    const float* v = (const float*)d_in[2];   // [1024]
    float* out = (float*)d_out;               // [wc 32*1024 | attn 32*2048]

    cvt_all_kernel<<<XBLOCKS + WBLOCKS, 256>>>(X, W);
    noop_kernel<<<1, 32>>>();                 // ncu alignment: -s 5 -> logits
    noop_kernel<<<1, 32>>>();

    cudaFuncSetAttribute(logits_kernel,
                         cudaFuncAttributeMaxDynamicSharedMemorySize, SMEM_BYTES);
    logits_kernel<<<GRID, 128, SMEM_BYTES>>>(v);
    softmax_kernel<<<BATCH, 256>>>(out);
    weighted_kernel<<<dim3(1, 16, BATCH), 128>>>(out);
}

// round 15
// speedup vs baseline: 1.0640x; 1.0176x over previous
#include <cuda_runtime.h>
#include <cuda_fp16.h>
#include <cstdint>

#define BDIM   1024
#define BATCH  32
#define SEQ    2048
#define MROWS  (BATCH * SEQ)

#define BM 128
#define BN 128
#define BK 64                      // fp16: 64 halves = 128B row (swizzle atom)
#define KTILES (BDIM / BK)         // 16 k-iterations per unit
#define NPASS  (BDIM / BN)         // 8 n-passes
#define MTILES (MROWS / BM)        // 512
#define UNITS  (MTILES * NPASS)    // 4096 work units (m-tile, n-pass)
#define GRID   304                 // 2 CTAs/SM x 152 SMs, persistent
#define NSTG   3
#define STG_A     16384            // 128 rows x 128B
#define STG_B     16384
#define STG_BYTES (STG_A + STG_B)  // 32768
#define SMEM_BYTES (NSTG * STG_BYTES + 256)   // ~96.5 KB -> 2 CTAs/SM

#define XBLOCKS ((MROWS * (BDIM / 8)) / 256)   // 32768
#define WBLOCKS ((BDIM * (BDIM / 8)) / 256)    // 512

__device__ __half g_Xh[(size_t)MROWS * BDIM];   // 128 MiB fp16 mirror of X
__device__ __half g_Wh[BDIM * BDIM];
__device__ float  g_logits[MROWS];

__device__ __forceinline__ uint32_t smem_u32(const void* p) {
    return (uint32_t)__cvta_generic_to_shared(p);
}
__device__ __forceinline__ void cp_async16(uint32_t saddr, const void* gaddr) {
    asm volatile("cp.async.cg.shared.global [%0], [%1], 16;\n" :: "r"(saddr), "l"(gaddr));
}
__device__ __forceinline__ uint32_t swz(uint32_t off) {   // SW128: bits[6:4] ^= bits[9:7]
    return off ^ ((off >> 3) & 0x70u);
}
__device__ __forceinline__ float tanh_ap(float x) {
    float y; asm("tanh.approx.f32 %0, %1;" : "=f"(y) : "f"(x)); return y;
}
__device__ __forceinline__ void ldsm_x4(uint32_t& r0, uint32_t& r1, uint32_t& r2,
                                        uint32_t& r3, uint32_t addr) {
    asm volatile("ldmatrix.sync.aligned.m8n8.x4.shared.b16 {%0,%1,%2,%3}, [%4];"
                 : "=r"(r0), "=r"(r1), "=r"(r2), "=r"(r3) : "r"(addr));
}

// ---------------------------------------------------------------------------
// fp32 -> fp16 bulk convert of X and W; W-half blocks also zero g_logits and
// the weighted-context region of out (both accumulated by atomics -> must be
// zeroed EVERY launch; graph replays the whole sequence).
// ---------------------------------------------------------------------------
__global__ void cvt_all_kernel(const float* __restrict__ X, const float* __restrict__ W,
                               float* __restrict__ out) {
    const float* src;
    __half* dst;
    size_t i;
    if (blockIdx.x < XBLOCKS) {
        src = X; dst = g_Xh;
        i = ((size_t)blockIdx.x * 256 + threadIdx.x) * 8;
    } else {
        src = W; dst = g_Wh;
        int z = (blockIdx.x - XBLOCKS) * 256 + threadIdx.x;   // 0..131071
        if (z < MROWS) g_logits[z] = 0.0f;
        if (z < BATCH * BDIM) out[z] = 0.0f;                   // wc region
        i = ((size_t)(blockIdx.x - XBLOCKS) * 256 + threadIdx.x) * 8;
    }
    float4 f0 = *(const float4*)(src + i);
    float4 f1 = *(const float4*)(src + i + 4);
    __half2 h[4];
    h[0] = __float22half2_rn({f0.x, f0.y});
    h[1] = __float22half2_rn({f0.z, f0.w});
    h[2] = __float22half2_rn({f1.x, f1.y});
    h[3] = __float22half2_rn({f1.z, f1.w});
    *(uint4*)(dst + i) = *(uint4*)h;
}

// ---------------------------------------------------------------------------
// tile loader for flat local iteration L of this CTA:
// unit u = bid + (L/16)*GRID, kt = L%16, m0 = (u/8)*128, nt = u%8.
// A (128 x 64 fp16) + B (128 x 64 fp16), SW128 smem; 16 cp.async/thread.
// ---------------------------------------------------------------------------
__device__ __forceinline__ void load_tile(char* smem, int L, int bid, int tid) {
    const int u  = bid + (L >> 4) * GRID;
    const int kt = L & (KTILES - 1);
    const int m0 = (u >> 3) * BM;
    const int nt = u & 7;
    const uint32_t base = smem_u32(smem) + (uint32_t)(L % NSTG) * STG_BYTES;
    const int r  = tid >> 3;                  // 0..15
    const int cb = (tid & 7) * 16;            // byte col in 128B row
    const __half* Xb = g_Xh + (size_t)(m0 + r) * BDIM + kt * BK + (cb >> 1);
    #pragma unroll
    for (int i = 0; i < 8; ++i) {
        uint32_t off = (uint32_t)(r + 16 * i) * 128u + (uint32_t)cb;
        cp_async16(base + swz(off), Xb + (size_t)(16 * i) * BDIM);
    }
    const __half* Wb = g_Wh + (size_t)(nt * BN + r) * BDIM + kt * BK + (cb >> 1);
    #pragma unroll
    for (int i = 0; i < 8; ++i) {
        uint32_t off = (uint32_t)(r + 16 * i) * 128u + (uint32_t)cb;
        cp_async16(base + STG_A + swz(off), Wb + (size_t)(16 * i) * BDIM);
    }
    asm volatile("cp.async.commit_group;\n" ::: "memory");
}

// ---------------------------------------------------------------------------
// Kernel A: logits[m] = sum_e v[e] * tanh( sum_d X[m,d] W[e,d] )
// Persistent static work queue, 304 CTAs, 3-stage ring, named-barrier
// arrive/sync split. NEW: ks=0 fragments of iteration L+1 are prefetched at
// the tail of iteration L (after wait_group), so each iteration opens with
// MMAs immediately after bar.sync -- no LDS-latency bubble at the front.
// ---------------------------------------------------------------------------
__global__ __launch_bounds__(128, 2)
void logits_kernel(const float* __restrict__ v) {
    extern __shared__ char smem[];

    const int tid  = threadIdx.x;
    const int warp = tid >> 5;
    const int lane = tid & 31;
    const int wm = warp >> 1;           // 0..1  -> 64-row group
    const int wn = warp & 1;            // 0..1  -> 64-col group
    const int l4 = lane & 3;
    const int lg = lane >> 2;
    const int bid = blockIdx.x;

    // units for this CTA: bid, bid+GRID, ...  (13 or 14)
    const int nu   = (UNITS - bid + GRID - 1) / GRID;
    const int LTOT = nu * KTILES;

    const uint32_t sb = smem_u32(smem);
    const uint32_t a_row = (uint32_t)(wm * 64 + (lane & 15));
    const uint32_t a_kb  = (uint32_t)((lane >> 4) * 16);
    const uint32_t b_idx = (uint32_t)(lane & 7);
    const uint32_t b_sel = (uint32_t)(lane >> 3);
    const uint32_t b_row = (uint32_t)(wn * 64 + (b_sel >> 1) * 8) + b_idx;
    const uint32_t b_kb  = (b_sel & 1) * 16u;

    // prologue: tiles 0, 1; make tile 0 visible to all threads
    load_tile(smem, 0, bid, tid);
    load_tile(smem, 1, bid, tid);
    asm volatile("cp.async.wait_group 1;" ::: "memory");
    __syncthreads();

    float part[8];
    #pragma unroll
    for (int p = 0; p < 8; ++p) part[p] = 0.0f;
    float acc[4][8][4];

    uint32_t af[4][16];   // transient fragments for ks = 1..3
    uint32_t bf[4][16];
    uint32_t pa[16];      // persistent prefetch: ks = 0 of the NEXT iteration
    uint32_t pb[16];

#define LDSM_KS(ks) do {                                                          \
    _Pragma("unroll")                                                             \
    for (int mi = 0; mi < 4; ++mi) {                                              \
        uint32_t off = (a_row + mi * 16u) * 128u + (uint32_t)((ks) * 32) + a_kb;  \
        ldsm_x4(af[ks][mi*4+0], af[ks][mi*4+1], af[ks][mi*4+2], af[ks][mi*4+3],   \
                stage + swz(off));                                                \
    }                                                                             \
    _Pragma("unroll")                                                             \
    for (int jj = 0; jj < 4; ++jj) {                                              \
        uint32_t off = (b_row + jj * 16u) * 128u + (uint32_t)((ks) * 32) + b_kb;  \
        ldsm_x4(bf[ks][jj*4+0], bf[ks][jj*4+1], bf[ks][jj*4+2], bf[ks][jj*4+3],   \
                stage + STG_A + swz(off));                                        \
    }                                                                             \
} while (0)

#define LDSM_PF(stg) do {                                                         \
    _Pragma("unroll")                                                             \
    for (int mi = 0; mi < 4; ++mi) {                                              \
        uint32_t off = (a_row + mi * 16u) * 128u + a_kb;                          \
        ldsm_x4(pa[mi*4+0], pa[mi*4+1], pa[mi*4+2], pa[mi*4+3], (stg) + swz(off)); \
    }                                                                             \
    _Pragma("unroll")                                                             \
    for (int jj = 0; jj < 4; ++jj) {                                              \
        uint32_t off = (b_row + jj * 16u) * 128u + b_kb;                          \
        ldsm_x4(pb[jj*4+0], pb[jj*4+1], pb[jj*4+2], pb[jj*4+3],                   \
                (stg) + STG_A + swz(off));                                        \
    }                                                                             \
} while (0)

#define MMA_KS(ks) do {                                                           \
    _Pragma("unroll")                                                             \
    for (int mi = 0; mi < 4; ++mi) {                                              \
        _Pragma("unroll")                                                         \
        for (int j = 0; j < 8; ++j) {                                             \
            asm volatile(                                                         \
                "mma.sync.aligned.m16n8k16.row.col.f32.f16.f16.f32 "              \
                "{%0,%1,%2,%3}, {%4,%5,%6,%7}, {%8,%9}, {%0,%1,%2,%3};\n"         \
                : "+f"(acc[mi][j][0]), "+f"(acc[mi][j][1]),                       \
                  "+f"(acc[mi][j][2]), "+f"(acc[mi][j][3])                        \
                : "r"(af[ks][mi*4+0]), "r"(af[ks][mi*4+1]),                       \
                  "r"(af[ks][mi*4+2]), "r"(af[ks][mi*4+3]),                       \
                  "r"(bf[ks][j*2+0]), "r"(bf[ks][j*2+1]));                        \
        }                                                                         \
    }                                                                             \
} while (0)

#define MMA_PF() do {                                                             \
    _Pragma("unroll")                                                             \
    for (int mi = 0; mi < 4; ++mi) {                                              \
        _Pragma("unroll")                                                         \
        for (int j = 0; j < 8; ++j) {                                             \
            asm volatile(                                                         \
                "mma.sync.aligned.m16n8k16.row.col.f32.f16.f16.f32 "              \
                "{%0,%1,%2,%3}, {%4,%5,%6,%7}, {%8,%9}, {%0,%1,%2,%3};\n"         \
                : "+f"(acc[mi][j][0]), "+f"(acc[mi][j][1]),                       \
                  "+f"(acc[mi][j][2]), "+f"(acc[mi][j][3])                        \
                : "r"(pa[mi*4+0]), "r"(pa[mi*4+1]),                               \
                  "r"(pa[mi*4+2]), "r"(pa[mi*4+3]),                               \
                  "r"(pb[j*2+0]), "r"(pb[j*2+1]));                                \
        }                                                                         \
    }                                                                             \
} while (0)

    // pre-loop prefetch of ks0 for iteration 0 (buffer 0 is ready)
    LDSM_PF(sb);

    for (int L = 0; L < LTOT; ++L) {
        const int kt = L & (KTILES - 1);

        // wait on the instance opened at iteration L-1 (ids 1 / 2)
        if (L > 0)
            asm volatile("bar.sync %0, %1;" :: "r"(1 + ((L - 1) & 1)), "r"(256) : "memory");

        if (L + 2 < LTOT) load_tile(smem, L + 2, bid, tid);

        if (kt == 0) {
            #pragma unroll
            for (int i = 0; i < 4; ++i)
                #pragma unroll
                for (int j = 0; j < 8; ++j)
                    #pragma unroll
                    for (int q = 0; q < 4; ++q) acc[i][j][q] = 0.0f;
        }

        const uint32_t stage = sb + (uint32_t)(L % NSTG) * STG_BYTES;

        LDSM_KS(1);
        MMA_PF();          // ks0 fragments were prefetched last iteration
        LDSM_KS(2);
        MMA_KS(1);
        LDSM_KS(3);
        MMA_KS(2);

        // my loads for tile L+1 are complete (keep L+2 pending)
        if (L < LTOT - 2) asm volatile("cp.async.wait_group 1;" ::: "memory");
        else              asm volatile("cp.async.wait_group 0;" ::: "memory");

        // signal: my ldsm of buffer L done + my tile-(L+1) loads landed
        if (L + 1 < LTOT) {
            asm volatile("bar.arrive %0, %1;" :: "r"(1 + (L & 1)), "r"(256) : "memory");
            // prefetch ks0 of iteration L+1 (tile L+1 proven landed above;
            // its buffer is not overwritten until iteration L+2, which the
            // barrier instance L+1 guards)
            const uint32_t nstage = sb + (uint32_t)((L + 1) % NSTG) * STG_BYTES;
            LDSM_PF(nstage);
        }

        MMA_KS(3);

        // unit epilogue: tanh + v-dot, reduce, atomicAdd into g_logits
        if (kt == KTILES - 1) {
            const int u  = bid + (L >> 4) * GRID;
            const int m0 = (u >> 3) * BM;
            const int nt = u & 7;
            #pragma unroll
            for (int j = 0; j < 8; ++j) {
                const int c = nt * BN + wn * 64 + j * 8 + l4 * 2;
                const float2 vv = *(const float2*)(v + c);   // one LDG.64, reused by all mi
                #pragma unroll
                for (int mi = 0; mi < 4; ++mi) {
                    part[mi * 2 + 0] += vv.x * tanh_ap(acc[mi][j][0])
                                      + vv.y * tanh_ap(acc[mi][j][1]);
                    part[mi * 2 + 1] += vv.x * tanh_ap(acc[mi][j][2])
                                      + vv.y * tanh_ap(acc[mi][j][3]);
                }
            }
            #pragma unroll
            for (int p = 0; p < 8; ++p) {
                part[p] += __shfl_xor_sync(0xffffffffu, part[p], 1);
                part[p] += __shfl_xor_sync(0xffffffffu, part[p], 2);
            }
            if (l4 == 0) {
                #pragma unroll
                for (int mi = 0; mi < 4; ++mi) {
                    int row = m0 + wm * 64 + mi * 16 + lg;
                    atomicAdd(&g_logits[row],     part[mi * 2 + 0]);
                    atomicAdd(&g_logits[row + 8], part[mi * 2 + 1]);
                }
            }
            #pragma unroll
            for (int p = 0; p < 8; ++p) part[p] = 0.0f;
        }
    }
#undef LDSM_KS
#undef LDSM_PF
#undef MMA_KS
#undef MMA_PF
}

// ---------------------------------------------------------------------------
// Kernel B: softmax over S=2048 per batch (bias b cancels; wc region is
// zeroed by cvt_all_kernel).
// ---------------------------------------------------------------------------
__global__ void softmax_kernel(float* __restrict__ out) {
    __shared__ float red[8];
    const int b = blockIdx.x;
    const int tid = threadIdx.x;
    const int warp = tid >> 5, lane = tid & 31;
    const float* lp = g_logits + b * SEQ;

    float vals[8];
    float m = -1e30f;
    #pragma unroll
    for (int i = 0; i < 8; ++i) { vals[i] = lp[i * 256 + tid]; m = fmaxf(m, vals[i]); }
    #pragma unroll
    for (int o = 16; o > 0; o >>= 1) m = fmaxf(m, __shfl_xor_sync(~0u, m, o));
    if (lane == 0) red[warp] = m;
    __syncthreads();
    float bm = red[0];
    #pragma unroll
    for (int w = 1; w < 8; ++w) bm = fmaxf(bm, red[w]);
    __syncthreads();

    float s = 0.0f;
    #pragma unroll
    for (int i = 0; i < 8; ++i) { vals[i] = __expf(vals[i] - bm); s += vals[i]; }
    #pragma unroll
    for (int o = 16; o > 0; o >>= 1) s += __shfl_xor_sync(~0u, s, o);
    if (lane == 0) red[warp] = s;
    __syncthreads();
    float ts = 0.0f;
    #pragma unroll
    for (int w = 0; w < 8; ++w) ts += red[w];

    float inv = 1.0f / ts;
    #pragma unroll
    for (int i = 0; i < 8; ++i)
        out[BATCH * BDIM + b * SEQ + i * 256 + tid] = vals[i] * inv;
}

// ---------------------------------------------------------------------------
// Kernel C: weighted_context[b,d] = sum_s attn[b,s] * X[b,s,d]
// 512 CTAs (16 s-chunks x 32 batches), 128 thr x 8 d's (one uint4/row),
// attn chunk staged in smem.
// ---------------------------------------------------------------------------
__global__ __launch_bounds__(128)
void weighted_kernel(float* __restrict__ out) {
    __shared__ float aw[128];
    const int b  = blockIdx.z;
    const int s0 = blockIdx.y * 128;
    const int d8 = threadIdx.x * 8;

    aw[threadIdx.x] = out[BATCH * BDIM + b * SEQ + s0 + threadIdx.x];
    __syncthreads();

    const __half* xb = g_Xh + ((size_t)b * SEQ + s0) * BDIM + d8;

    float acc[8] = {0.f, 0.f, 0.f, 0.f, 0.f, 0.f, 0.f, 0.f};
    #pragma unroll 4
    for (int s = 0; s < 128; ++s) {
        uint4 raw = *(const uint4*)(xb + (size_t)s * BDIM);
        const __half2* h = (const __half2*)&raw;
        float w = aw[s];
        #pragma unroll
        for (int q = 0; q < 4; ++q) {
            float2 x = __half22float2(h[q]);
            acc[2*q]     += w * x.x;
            acc[2*q + 1] += w * x.y;
        }
    }
    #pragma unroll
    for (int q = 0; q < 8; ++q)
        atomicAdd(&out[b * BDIM + d8 + q], acc[q]);
}

// ---------------------------------------------------------------------------
extern "C" void kernel_launch(void* const* d_in, const int* in_sizes, int n_in,
                              void* d_out, int out_size) {
    const float* X = (const float*)d_in[0];   // context [32,2048,1024]
    const float* W = (const float*)d_in[1];   // [1024,1024]
    const float* v = (const float*)d_in[2];   // [1024]
    float* out = (float*)d_out;               // [wc 32*1024 | attn 32*2048]

    cvt_all_kernel<<<XBLOCKS + WBLOCKS, 256>>>(X, W, out);

    cudaFuncSetAttribute(logits_kernel,
                         cudaFuncAttributeMaxDynamicSharedMemorySize, SMEM_BYTES);
    logits_kernel<<<GRID, 128, SMEM_BYTES>>>(v);
    softmax_kernel<<<BATCH, 256>>>(out);
    weighted_kernel<<<dim3(1, 16, BATCH), 128>>>(out);
}

// round 16
// speedup vs baseline: 1.1000x; 1.0339x over previous
#include <cuda_runtime.h>
#include <cuda_fp16.h>
#include <cstdint>

#define BDIM   1024
#define BATCH  32
#define SEQ    2048
#define MROWS  (BATCH * SEQ)

#define BM 128
#define BN 128
#define BK 64                      // fp16: 64 halves = 128B row (swizzle atom)
#define KTILES (BDIM / BK)         // 16 k-iterations per unit
#define NPASS  (BDIM / BN)         // 8 n-passes
#define MTILES (MROWS / BM)        // 512
#define UNITS  (MTILES * NPASS)    // 4096 work units (m-tile, n-pass)
#define GRID   304                 // 2 CTAs/SM x 152 SMs, persistent
#define NSTG   3
#define STG_A     16384            // 128 rows x 128B
#define STG_B     16384
#define STG_BYTES (STG_A + STG_B)  // 32768
#define SMEM_BYTES (NSTG * STG_BYTES + 256)   // ~96.5 KB -> 2 CTAs/SM

#define XBLOCKS ((MROWS * (BDIM / 8)) / 256)   // 32768
#define WBLOCKS ((BDIM * (BDIM / 8)) / 256)    // 512

__device__ __half g_Xh[(size_t)MROWS * BDIM];   // 128 MiB fp16 mirror of X
__device__ __half g_Wh[BDIM * BDIM];
__device__ float  g_logits[MROWS];

__device__ __forceinline__ uint32_t smem_u32(const void* p) {
    return (uint32_t)__cvta_generic_to_shared(p);
}
__device__ __forceinline__ void cp_async16(uint32_t saddr, const void* gaddr) {
    asm volatile("cp.async.cg.shared.global [%0], [%1], 16;\n" :: "r"(saddr), "l"(gaddr));
}
__device__ __forceinline__ uint32_t swz(uint32_t off) {   // SW128: bits[6:4] ^= bits[9:7]
    return off ^ ((off >> 3) & 0x70u);
}
__device__ __forceinline__ float tanh_ap(float x) {
    float y; asm("tanh.approx.f32 %0, %1;" : "=f"(y) : "f"(x)); return y;
}
__device__ __forceinline__ void ldsm_x4(uint32_t& r0, uint32_t& r1, uint32_t& r2,
                                        uint32_t& r3, uint32_t addr) {
    asm volatile("ldmatrix.sync.aligned.m8n8.x4.shared.b16 {%0,%1,%2,%3}, [%4];"
                 : "=r"(r0), "=r"(r1), "=r"(r2), "=r"(r3) : "r"(addr));
}

// ---------------------------------------------------------------------------
// fp32 -> fp16 bulk convert of X and W; W-half blocks also zero g_logits and
// the weighted-context region of out (both accumulated by atomics -> must be
// zeroed EVERY launch; graph replays the whole sequence).
// ---------------------------------------------------------------------------
__global__ void cvt_all_kernel(const float* __restrict__ X, const float* __restrict__ W,
                               float* __restrict__ out) {
    const float* src;
    __half* dst;
    size_t i;
    if (blockIdx.x < XBLOCKS) {
        src = X; dst = g_Xh;
        i = ((size_t)blockIdx.x * 256 + threadIdx.x) * 8;
    } else {
        src = W; dst = g_Wh;
        int z = (blockIdx.x - XBLOCKS) * 256 + threadIdx.x;   // 0..131071
        if (z < MROWS) g_logits[z] = 0.0f;
        if (z < BATCH * BDIM) out[z] = 0.0f;                   // wc region
        i = ((size_t)(blockIdx.x - XBLOCKS) * 256 + threadIdx.x) * 8;
    }
    float4 f0 = *(const float4*)(src + i);
    float4 f1 = *(const float4*)(src + i + 4);
    __half2 h[4];
    h[0] = __float22half2_rn({f0.x, f0.y});
    h[1] = __float22half2_rn({f0.z, f0.w});
    h[2] = __float22half2_rn({f1.x, f1.y});
    h[3] = __float22half2_rn({f1.z, f1.w});
    *(uint4*)(dst + i) = *(uint4*)h;
}

// ---------------------------------------------------------------------------
// tile loader for flat local iteration L of this CTA:
// unit u = bid + (L/16)*GRID, kt = L%16, m0 = (u/8)*128, nt = u%8.
// A (128 x 64 fp16) + B (128 x 64 fp16), SW128 smem; 16 cp.async/thread.
// ---------------------------------------------------------------------------
__device__ __forceinline__ void load_tile(char* smem, int L, int bid, int tid) {
    const int u  = bid + (L >> 4) * GRID;
    const int kt = L & (KTILES - 1);
    const int m0 = (u >> 3) * BM;
    const int nt = u & 7;
    const uint32_t base = smem_u32(smem) + (uint32_t)(L % NSTG) * STG_BYTES;
    const int r  = tid >> 3;                  // 0..15
    const int cb = (tid & 7) * 16;            // byte col in 128B row
    const __half* Xb = g_Xh + (size_t)(m0 + r) * BDIM + kt * BK + (cb >> 1);
    #pragma unroll
    for (int i = 0; i < 8; ++i) {
        uint32_t off = (uint32_t)(r + 16 * i) * 128u + (uint32_t)cb;
        cp_async16(base + swz(off), Xb + (size_t)(16 * i) * BDIM);
    }
    const __half* Wb = g_Wh + (size_t)(nt * BN + r) * BDIM + kt * BK + (cb >> 1);
    #pragma unroll
    for (int i = 0; i < 8; ++i) {
        uint32_t off = (uint32_t)(r + 16 * i) * 128u + (uint32_t)cb;
        cp_async16(base + STG_A + swz(off), Wb + (size_t)(16 * i) * BDIM);
    }
    asm volatile("cp.async.commit_group;\n" ::: "memory");
}

// ---------------------------------------------------------------------------
// Kernel A: logits[m] = sum_e v[e] * tanh( sum_d X[m,d] W[e,d] )
// Persistent static work queue, 304 CTAs, 3-stage ring, named-barrier
// arrive/sync split, ks0 fragments of iteration L+1 prefetched at the tail
// of iteration L (no LDS-latency bubble at the iteration front).
// ---------------------------------------------------------------------------
__global__ __launch_bounds__(128, 2)
void logits_kernel(const float* __restrict__ v) {
    extern __shared__ char smem[];

    const int tid  = threadIdx.x;
    const int warp = tid >> 5;
    const int lane = tid & 31;
    const int wm = warp >> 1;           // 0..1  -> 64-row group
    const int wn = warp & 1;            // 0..1  -> 64-col group
    const int l4 = lane & 3;
    const int lg = lane >> 2;
    const int bid = blockIdx.x;

    // units for this CTA: bid, bid+GRID, ...  (13 or 14)
    const int nu   = (UNITS - bid + GRID - 1) / GRID;
    const int LTOT = nu * KTILES;

    const uint32_t sb = smem_u32(smem);
    const uint32_t a_row = (uint32_t)(wm * 64 + (lane & 15));
    const uint32_t a_kb  = (uint32_t)((lane >> 4) * 16);
    const uint32_t b_idx = (uint32_t)(lane & 7);
    const uint32_t b_sel = (uint32_t)(lane >> 3);
    const uint32_t b_row = (uint32_t)(wn * 64 + (b_sel >> 1) * 8) + b_idx;
    const uint32_t b_kb  = (b_sel & 1) * 16u;

    // prologue: tiles 0, 1; make tile 0 visible to all threads
    load_tile(smem, 0, bid, tid);
    load_tile(smem, 1, bid, tid);
    asm volatile("cp.async.wait_group 1;" ::: "memory");
    __syncthreads();

    float part[8];
    #pragma unroll
    for (int p = 0; p < 8; ++p) part[p] = 0.0f;
    float acc[4][8][4];

    uint32_t af[4][16];   // transient fragments for ks = 1..3
    uint32_t bf[4][16];
    uint32_t pa[16];      // persistent prefetch: ks = 0 of the NEXT iteration
    uint32_t pb[16];

#define LDSM_KS(ks) do {                                                          \
    _Pragma("unroll")                                                             \
    for (int mi = 0; mi < 4; ++mi) {                                              \
        uint32_t off = (a_row + mi * 16u) * 128u + (uint32_t)((ks) * 32) + a_kb;  \
        ldsm_x4(af[ks][mi*4+0], af[ks][mi*4+1], af[ks][mi*4+2], af[ks][mi*4+3],   \
                stage + swz(off));                                                \
    }                                                                             \
    _Pragma("unroll")                                                             \
    for (int jj = 0; jj < 4; ++jj) {                                              \
        uint32_t off = (b_row + jj * 16u) * 128u + (uint32_t)((ks) * 32) + b_kb;  \
        ldsm_x4(bf[ks][jj*4+0], bf[ks][jj*4+1], bf[ks][jj*4+2], bf[ks][jj*4+3],   \
                stage + STG_A + swz(off));                                        \
    }                                                                             \
} while (0)

#define LDSM_PF(stg) do {                                                         \
    _Pragma("unroll")                                                             \
    for (int mi = 0; mi < 4; ++mi) {                                              \
        uint32_t off = (a_row + mi * 16u) * 128u + a_kb;                          \
        ldsm_x4(pa[mi*4+0], pa[mi*4+1], pa[mi*4+2], pa[mi*4+3], (stg) + swz(off)); \
    }                                                                             \
    _Pragma("unroll")                                                             \
    for (int jj = 0; jj < 4; ++jj) {                                              \
        uint32_t off = (b_row + jj * 16u) * 128u + b_kb;                          \
        ldsm_x4(pb[jj*4+0], pb[jj*4+1], pb[jj*4+2], pb[jj*4+3],                   \
                (stg) + STG_A + swz(off));                                        \
    }                                                                             \
} while (0)

#define MMA_KS(ks) do {                                                           \
    _Pragma("unroll")                                                             \
    for (int mi = 0; mi < 4; ++mi) {                                              \
        _Pragma("unroll")                                                         \
        for (int j = 0; j < 8; ++j) {                                             \
            asm volatile(                                                         \
                "mma.sync.aligned.m16n8k16.row.col.f32.f16.f16.f32 "              \
                "{%0,%1,%2,%3}, {%4,%5,%6,%7}, {%8,%9}, {%0,%1,%2,%3};\n"         \
                : "+f"(acc[mi][j][0]), "+f"(acc[mi][j][1]),                       \
                  "+f"(acc[mi][j][2]), "+f"(acc[mi][j][3])                        \
                : "r"(af[ks][mi*4+0]), "r"(af[ks][mi*4+1]),                       \
                  "r"(af[ks][mi*4+2]), "r"(af[ks][mi*4+3]),                       \
                  "r"(bf[ks][j*2+0]), "r"(bf[ks][j*2+1]));                        \
        }                                                                         \
    }                                                                             \
} while (0)

#define MMA_PF() do {                                                             \
    _Pragma("unroll")                                                             \
    for (int mi = 0; mi < 4; ++mi) {                                              \
        _Pragma("unroll")                                                         \
        for (int j = 0; j < 8; ++j) {                                             \
            asm volatile(                                                         \
                "mma.sync.aligned.m16n8k16.row.col.f32.f16.f16.f32 "              \
                "{%0,%1,%2,%3}, {%4,%5,%6,%7}, {%8,%9}, {%0,%1,%2,%3};\n"         \
                : "+f"(acc[mi][j][0]), "+f"(acc[mi][j][1]),                       \
                  "+f"(acc[mi][j][2]), "+f"(acc[mi][j][3])                        \
                : "r"(pa[mi*4+0]), "r"(pa[mi*4+1]),                               \
                  "r"(pa[mi*4+2]), "r"(pa[mi*4+3]),                               \
                  "r"(pb[j*2+0]), "r"(pb[j*2+1]));                                \
        }                                                                         \
    }                                                                             \
} while (0)

    // pre-loop prefetch of ks0 for iteration 0 (buffer 0 is ready)
    LDSM_PF(sb);

    for (int L = 0; L < LTOT; ++L) {
        const int kt = L & (KTILES - 1);

        // wait on the instance opened at iteration L-1 (ids 1 / 2)
        if (L > 0)
            asm volatile("bar.sync %0, %1;" :: "r"(1 + ((L - 1) & 1)), "r"(256) : "memory");

        if (L + 2 < LTOT) load_tile(smem, L + 2, bid, tid);

        if (kt == 0) {
            #pragma unroll
            for (int i = 0; i < 4; ++i)
                #pragma unroll
                for (int j = 0; j < 8; ++j)
                    #pragma unroll
                    for (int q = 0; q < 4; ++q) acc[i][j][q] = 0.0f;
        }

        const uint32_t stage = sb + (uint32_t)(L % NSTG) * STG_BYTES;

        LDSM_KS(1);
        MMA_PF();          // ks0 fragments were prefetched last iteration
        LDSM_KS(2);
        MMA_KS(1);
        LDSM_KS(3);
        MMA_KS(2);

        // my loads for tile L+1 are complete (keep L+2 pending)
        if (L < LTOT - 2) asm volatile("cp.async.wait_group 1;" ::: "memory");
        else              asm volatile("cp.async.wait_group 0;" ::: "memory");

        // signal: my ldsm of buffer L done + my tile-(L+1) loads landed
        if (L + 1 < LTOT) {
            asm volatile("bar.arrive %0, %1;" :: "r"(1 + (L & 1)), "r"(256) : "memory");
            // prefetch ks0 of iteration L+1 (tile L+1 proven landed above;
            // its buffer is not overwritten until iteration L+2, which the
            // barrier instance L+1 guards)
            const uint32_t nstage = sb + (uint32_t)((L + 1) % NSTG) * STG_BYTES;
            LDSM_PF(nstage);
        }

        MMA_KS(3);

        // unit epilogue: tanh + v-dot, reduce, atomicAdd into g_logits
        if (kt == KTILES - 1) {
            const int u  = bid + (L >> 4) * GRID;
            const int m0 = (u >> 3) * BM;
            const int nt = u & 7;
            #pragma unroll
            for (int j = 0; j < 8; ++j) {
                const int c = nt * BN + wn * 64 + j * 8 + l4 * 2;
                const float2 vv = *(const float2*)(v + c);   // one LDG.64, reused by all mi
                #pragma unroll
                for (int mi = 0; mi < 4; ++mi) {
                    part[mi * 2 + 0] += vv.x * tanh_ap(acc[mi][j][0])
                                      + vv.y * tanh_ap(acc[mi][j][1]);
                    part[mi * 2 + 1] += vv.x * tanh_ap(acc[mi][j][2])
                                      + vv.y * tanh_ap(acc[mi][j][3]);
                }
            }
            #pragma unroll
            for (int p = 0; p < 8; ++p) {
                part[p] += __shfl_xor_sync(0xffffffffu, part[p], 1);
                part[p] += __shfl_xor_sync(0xffffffffu, part[p], 2);
            }
            if (l4 == 0) {
                #pragma unroll
                for (int mi = 0; mi < 4; ++mi) {
                    int row = m0 + wm * 64 + mi * 16 + lg;
                    atomicAdd(&g_logits[row],     part[mi * 2 + 0]);
                    atomicAdd(&g_logits[row + 8], part[mi * 2 + 1]);
                }
            }
            #pragma unroll
            for (int p = 0; p < 8; ++p) part[p] = 0.0f;
        }
    }
#undef LDSM_KS
#undef LDSM_PF
#undef MMA_KS
#undef MMA_PF
}

// ---------------------------------------------------------------------------
// Kernel B: softmax over S=2048 per batch (bias b cancels; wc region is
// zeroed by cvt_all_kernel).
// ---------------------------------------------------------------------------
__global__ void softmax_kernel(float* __restrict__ out) {
    __shared__ float red[8];
    const int b = blockIdx.x;
    const int tid = threadIdx.x;
    const int warp = tid >> 5, lane = tid & 31;
    const float* lp = g_logits + b * SEQ;

    float vals[8];
    float m = -1e30f;
    #pragma unroll
    for (int i = 0; i < 8; ++i) { vals[i] = lp[i * 256 + tid]; m = fmaxf(m, vals[i]); }
    #pragma unroll
    for (int o = 16; o > 0; o >>= 1) m = fmaxf(m, __shfl_xor_sync(~0u, m, o));
    if (lane == 0) red[warp] = m;
    __syncthreads();
    float bm = red[0];
    #pragma unroll
    for (int w = 1; w < 8; ++w) bm = fmaxf(bm, red[w]);
    __syncthreads();

    float s = 0.0f;
    #pragma unroll
    for (int i = 0; i < 8; ++i) { vals[i] = __expf(vals[i] - bm); s += vals[i]; }
    #pragma unroll
    for (int o = 16; o > 0; o >>= 1) s += __shfl_xor_sync(~0u, s, o);
    if (lane == 0) red[warp] = s;
    __syncthreads();
    float ts = 0.0f;
    #pragma unroll
    for (int w = 0; w < 8; ++w) ts += red[w];

    float inv = 1.0f / ts;
    #pragma unroll
    for (int i = 0; i < 8; ++i)
        out[BATCH * BDIM + b * SEQ + i * 256 + tid] = vals[i] * inv;
}

// ---------------------------------------------------------------------------
// Kernel C: weighted_context[b,d] = sum_s attn[b,s] * X[b,s,d]
// 1024 CTAs (32 s-chunks of 64 x 32 batches), 128 thr x 8 d's (one
// uint4/row), attn chunk staged in smem. 4x the CTAs of round 15 -> enough
// outstanding loads to approach the HBM roof.
// ---------------------------------------------------------------------------
__global__ __launch_bounds__(128)
void weighted_kernel(float* __restrict__ out) {
    __shared__ float aw[64];
    const int b  = blockIdx.z;
    const int s0 = blockIdx.y * 64;
    const int d8 = threadIdx.x * 8;

    if (threadIdx.x < 64)
        aw[threadIdx.x] = out[BATCH * BDIM + b * SEQ + s0 + threadIdx.x];
    __syncthreads();

    const __half* xb = g_Xh + ((size_t)b * SEQ + s0) * BDIM + d8;

    float acc[8] = {0.f, 0.f, 0.f, 0.f, 0.f, 0.f, 0.f, 0.f};
    #pragma unroll 8
    for (int s = 0; s < 64; ++s) {
        uint4 raw = *(const uint4*)(xb + (size_t)s * BDIM);
        const __half2* h = (const __half2*)&raw;
        float w = aw[s];
        #pragma unroll
        for (int q = 0; q < 4; ++q) {
            float2 x = __half22float2(h[q]);
            acc[2*q]     += w * x.x;
            acc[2*q + 1] += w * x.y;
        }
    }
    #pragma unroll
    for (int q = 0; q < 8; ++q)
        atomicAdd(&out[b * BDIM + d8 + q], acc[q]);
}

// ---------------------------------------------------------------------------
extern "C" void kernel_launch(void* const* d_in, const int* in_sizes, int n_in,
                              void* d_out, int out_size) {
    const float* X = (const float*)d_in[0];   // context [32,2048,1024]
    const float* W = (const float*)d_in[1];   // [1024,1024]
    const float* v = (const float*)d_in[2];   // [1024]
    float* out = (float*)d_out;               // [wc 32*1024 | attn 32*2048]

    cvt_all_kernel<<<XBLOCKS + WBLOCKS, 256>>>(X, W, out);

    cudaFuncSetAttribute(logits_kernel,
                         cudaFuncAttributeMaxDynamicSharedMemorySize, SMEM_BYTES);
    logits_kernel<<<GRID, 128, SMEM_BYTES>>>(v);
    softmax_kernel<<<BATCH, 256>>>(out);
    weighted_kernel<<<dim3(1, 32, BATCH), 128>>>(out);
}